// round 1
// baseline (speedup 1.0000x reference)
#include <cuda_runtime.h>
#include <cstdint>
#include <cmath>

// Problem shape (fixed by the dataset):
//   x  : [B=4, S=2048, H=2048]  -> tokens N = 8192, H = 2048
//   Wg : [I=8192, H=2048]
//   Wu : [I=8192, H=2048]
//   Wd : [H=2048, I=8192]
//   act_channels = 2048 (top-k over I per token)
//   out: [N, H] fp32
#define NTOK 8192
#define HDIM 2048
#define IDIM 8192
#define KSEL 2048

// Scratch (device globals: allocation inside kernel_launch is forbidden).
__device__ float g_gate[(size_t)NTOK * IDIM]; // gate logits
__device__ float g_act [(size_t)NTOK * IDIM]; // up projection v, then scaled (in place)

// ---------------------------------------------------------------------------
// SGEMM:  C[m][n] = sum_k A[m][k] * B[n][k]
// A: [M,K] row-major, B: [N,K] row-major, C: [M,N] row-major.
// Tiles: BM=BN=128, BK=16, 256 threads, 8x8 per-thread microtile.
// All dims divisible by tile sizes for this problem -> no bounds checks.
// ---------------------------------------------------------------------------
#define BM 128
#define BN 128
#define BK 16
#define TM 8
#define TN 8

__global__ __launch_bounds__(256, 2)
void sgemm_tt(const float* __restrict__ A,
              const float* __restrict__ B,
              float* __restrict__ C,
              int M, int N, int K)
{
    __shared__ float As[BK][BM + 4];
    __shared__ float Bs[BK][BN + 4];

    const int bm = blockIdx.y * BM;
    const int bn = blockIdx.x * BN;
    const int tid = threadIdx.x;
    const int tx = tid % 16;      // column group
    const int ty = tid / 16;      // row group

    float acc[TM][TN];
#pragma unroll
    for (int i = 0; i < TM; i++)
#pragma unroll
        for (int j = 0; j < TN; j++) acc[i][j] = 0.f;

    const int lr = tid >> 2;            // 0..63
    const int lc = (tid & 3) * 4;       // 0,4,8,12

    for (int k0 = 0; k0 < K; k0 += BK) {
        // Load A tile (128x16), store transposed As[k][m]
#pragma unroll
        for (int l = 0; l < 2; l++) {
            int r = lr + l * 64;
            float4 v = *(const float4*)(A + (size_t)(bm + r) * K + k0 + lc);
            As[lc + 0][r] = v.x; As[lc + 1][r] = v.y;
            As[lc + 2][r] = v.z; As[lc + 3][r] = v.w;
        }
        // Load B tile (128x16), store transposed Bs[k][n]
#pragma unroll
        for (int l = 0; l < 2; l++) {
            int r = lr + l * 64;
            float4 v = *(const float4*)(B + (size_t)(bn + r) * K + k0 + lc);
            Bs[lc + 0][r] = v.x; Bs[lc + 1][r] = v.y;
            Bs[lc + 2][r] = v.z; Bs[lc + 3][r] = v.w;
        }
        __syncthreads();

#pragma unroll
        for (int k = 0; k < BK; k++) {
            float a[TM], b[TN];
#pragma unroll
            for (int i = 0; i < TM; i++) a[i] = As[k][ty * TM + i];
#pragma unroll
            for (int j = 0; j < TN; j++) b[j] = Bs[k][tx * TN + j];
#pragma unroll
            for (int i = 0; i < TM; i++)
#pragma unroll
                for (int j = 0; j < TN; j++)
                    acc[i][j] = fmaf(a[i], b[j], acc[i][j]);
        }
        __syncthreads();
    }

#pragma unroll
    for (int i = 0; i < TM; i++) {
#pragma unroll
        for (int j = 0; j < TN; j += 4) {
            float4 v = make_float4(acc[i][j], acc[i][j + 1], acc[i][j + 2], acc[i][j + 3]);
            *(float4*)(C + (size_t)(bm + ty * TM + i) * N + bn + tx * TN + j) = v;
        }
    }
}

// ---------------------------------------------------------------------------
// Per-token top-K select + silu(gate)*v scatter (in place over v).
// One CTA (256 threads) per token row. Exact k-th-largest via 4-pass 8-bit
// radix select on the order-preserving uint mapping of float.
// ---------------------------------------------------------------------------
__global__ __launch_bounds__(256)
void topk_select_kernel(const float* __restrict__ gate, float* __restrict__ act)
{
    __shared__ unsigned s_u[IDIM];      // 32 KB: sortable keys for this row
    __shared__ int      hist[256];
    __shared__ unsigned s_prefix;
    __shared__ int      s_kk;
    __shared__ int      s_adm;

    const int row = blockIdx.x;
    const int tid = threadIdx.x;
    const float* grow = gate + (size_t)row * IDIM;
    float*       arow = act  + (size_t)row * IDIM;

    // Map float -> order-preserving unsigned key.
    for (int i = tid; i < IDIM; i += 256) {
        unsigned b = __float_as_uint(grow[i]);
        s_u[i] = (b & 0x80000000u) ? ~b : (b | 0x80000000u);
    }
    if (tid == 0) { s_prefix = 0u; s_kk = KSEL; s_adm = 0; }
    __syncthreads();

    // 4-pass MSB radix select for the KSEL-th largest key.
#pragma unroll
    for (int pass = 0; pass < 4; pass++) {
        const int shift = 24 - 8 * pass;
        hist[tid] = 0;
        __syncthreads();
        const unsigned prefix = s_prefix;
        const unsigned himask = (pass == 0) ? 0u : (0xFFFFFFFFu << (shift + 8));
        for (int i = tid; i < IDIM; i += 256) {
            unsigned u = s_u[i];
            if ((u & himask) == prefix)
                atomicAdd(&hist[(u >> shift) & 255], 1);
        }
        __syncthreads();
        if (tid == 0) {
            int kk = s_kk, cum = 0, b = 0;
            for (int x = 255; x >= 0; x--) {
                cum += hist[x];
                if (cum >= kk) { b = x; break; }
            }
            s_kk = kk - (cum - hist[b]);          // rank within the equal group
            s_prefix = prefix | ((unsigned)b << shift);
        }
        __syncthreads();
    }

    const unsigned t = s_prefix;   // exact bit pattern of the KSEL-th largest key
    const int eq_quota = s_kk;     // how many keys == t to admit
    __syncthreads();

    // Select & fuse: scaled = silu(gate) * v for selected channels, else 0.
    for (int i = tid; i < IDIM; i += 256) {
        const unsigned u = s_u[i];
        bool sel = (u > t);
        if (u == t) {
            if (atomicAdd(&s_adm, 1) < eq_quota) sel = true;
        }
        float o = 0.f;
        if (sel) {
            unsigned b = (u & 0x80000000u) ? (u & 0x7FFFFFFFu) : ~u;
            float g = __uint_as_float(b);
            float s = g / (1.f + expf(-g));       // silu
            o = s * arow[i];
        }
        arow[i] = o;
    }
}

// ---------------------------------------------------------------------------
extern "C" void kernel_launch(void* const* d_in, const int* in_sizes, int n_in,
                              void* d_out, int out_size)
{
    const float* x  = (const float*)d_in[0];   // [NTOK, HDIM]
    const float* Wg = (const float*)d_in[1];   // [IDIM, HDIM]
    const float* Wu = (const float*)d_in[2];   // [IDIM, HDIM]
    const float* Wd = (const float*)d_in[3];   // [HDIM, IDIM]
    float* out = (float*)d_out;                // [NTOK, HDIM]

    float* gate = nullptr;
    float* act  = nullptr;
    cudaGetSymbolAddress((void**)&gate, g_gate);
    cudaGetSymbolAddress((void**)&act,  g_act);

    dim3 block(256);

    // GEMM1a: gate = x @ Wg^T   [NTOK, IDIM], K = HDIM
    {
        dim3 grid(IDIM / BN, NTOK / BM);
        sgemm_tt<<<grid, block>>>(x, Wg, gate, NTOK, IDIM, HDIM);
    }
    // GEMM1b: v = x @ Wu^T
    {
        dim3 grid(IDIM / BN, NTOK / BM);
        sgemm_tt<<<grid, block>>>(x, Wu, act, NTOK, IDIM, HDIM);
    }
    // Top-K select + silu*v (act becomes the scaled/scattered tensor)
    {
        topk_select_kernel<<<NTOK, block>>>(gate, act);
    }
    // GEMM2: out = scaled @ Wd^T   [NTOK, HDIM], K = IDIM
    {
        dim3 grid(HDIM / BN, NTOK / BM);
        sgemm_tt<<<grid, block>>>(act, Wd, out, NTOK, HDIM, IDIM);
    }
}